// round 11
// baseline (speedup 1.0000x reference)
#include <cuda_runtime.h>
#include <cstdint>

// Problem constants
#define BATCH   4
#define SEQ     2048
#define DMODEL  1024
#define NHEADS  16
#define HDIM    64
#define MTOT    (BATCH * SEQ)   // 8192

// -------------------- scratch (device globals; no allocation) --------------------
__device__ __align__(16) float g_q[BATCH * NHEADS * SEQ * HDIM];   // [B*H, S, 64]
__device__ __align__(16) float g_k[BATCH * NHEADS * SEQ * HDIM];
__device__ __align__(16) float g_v[BATCH * NHEADS * SEQ * HDIM];
__device__ __align__(16) float g_ao[MTOT * DMODEL];                // [B, S, D]

// -------------------- helpers --------------------
__device__ __forceinline__ uint32_t f2tf(float x) {
    uint32_t r;
    asm("cvt.rna.tf32.f32 %0, %1;" : "=r"(r) : "f"(x));
    return r;
}

// D += A(16x8) * B(8x8), tf32 inputs, f32 accumulate
__device__ __forceinline__ void mma8(float* c, const uint32_t* a, const uint32_t* b) {
    asm volatile(
        "mma.sync.aligned.m16n8k8.row.col.f32.tf32.tf32.f32 "
        "{%0,%1,%2,%3}, {%4,%5,%6,%7}, {%8,%9}, {%0,%1,%2,%3};\n"
        : "+f"(c[0]), "+f"(c[1]), "+f"(c[2]), "+f"(c[3])
        : "r"(a[0]), "r"(a[1]), "r"(a[2]), "r"(a[3]),
          "r"(b[0]), "r"(b[1]));
}

// ==================== TF32 GEMM: C[M,N] = X[M,K] @ W[N,K]^T + bias ====================
// mode: 0 = plain [M,N] row-major into `out` (X==nullptr means read g_ao)
//       1/2/3 = scatter into g_q/g_k/g_v with [B*H, S, 64] layout
#define GBM  128
#define GBN  128
#define GBK  32
#define GPAD 36   // 36*4B rows: frag load bank = (4g+tg) -> conflict-free; rows 16B-aligned

__global__ __launch_bounds__(256, 1)
void gemm_tf32(const float* __restrict__ X, const float* __restrict__ W,
               const float* __restrict__ bias, float* __restrict__ out, int mode)
{
    __shared__ uint32_t As[GBM * GPAD];
    __shared__ uint32_t Bs[GBN * GPAD];

    const float* Xp = X ? X : g_ao;
    float* obase;
    if (mode == 1)      obase = g_q;
    else if (mode == 2) obase = g_k;
    else if (mode == 3) obase = g_v;
    else                obase = out;

    const int tid  = threadIdx.x;
    const int lane = tid & 31;
    const int wid  = tid >> 5;
    const int g    = lane >> 2;
    const int tg   = lane & 3;
    const int wm   = (wid >> 2) * 64;   // warp M offset (2 warps in M)
    const int wn   = (wid & 3) * 32;    // warp N offset (4 warps in N)
    const int bm   = blockIdx.x * GBM;
    const int bn   = blockIdx.y * GBN;

    float acc[4][4][4];
#pragma unroll
    for (int i = 0; i < 4; i++)
#pragma unroll
        for (int j = 0; j < 4; j++)
#pragma unroll
            for (int r = 0; r < 4; r++) acc[i][j][r] = 0.f;

    for (int k0 = 0; k0 < DMODEL; k0 += GBK) {
        // global -> smem (convert to tf32 on the way); 1024 float4 per tile, 4/thread
#pragma unroll
        for (int i = 0; i < 4; i++) {
            int e   = tid + i * 256;
            int row = e >> 3;
            int c4  = (e & 7) << 2;
            float4 va = *(const float4*)(Xp + (size_t)(bm + row) * DMODEL + k0 + c4);
            uint4  ua = make_uint4(f2tf(va.x), f2tf(va.y), f2tf(va.z), f2tf(va.w));
            *(uint4*)(&As[row * GPAD + c4]) = ua;
            float4 vb = *(const float4*)(W + (size_t)(bn + row) * DMODEL + k0 + c4);
            uint4  ub = make_uint4(f2tf(vb.x), f2tf(vb.y), f2tf(vb.z), f2tf(vb.w));
            *(uint4*)(&Bs[row * GPAD + c4]) = ub;
        }
        __syncthreads();

#pragma unroll
        for (int ks = 0; ks < 4; ks++) {
            const int kk = ks * 8;
            uint32_t a[4][4], bb[4][2];
#pragma unroll
            for (int mt = 0; mt < 4; mt++) {
                int r0 = wm + mt * 16;
                a[mt][0] = As[(r0 + g)     * GPAD + kk + tg];
                a[mt][1] = As[(r0 + g + 8) * GPAD + kk + tg];
                a[mt][2] = As[(r0 + g)     * GPAD + kk + tg + 4];
                a[mt][3] = As[(r0 + g + 8) * GPAD + kk + tg + 4];
            }
#pragma unroll
            for (int nt = 0; nt < 4; nt++) {
                int rn = wn + nt * 8 + g;
                bb[nt][0] = Bs[rn * GPAD + kk + tg];
                bb[nt][1] = Bs[rn * GPAD + kk + tg + 4];
            }
#pragma unroll
            for (int mt = 0; mt < 4; mt++)
#pragma unroll
                for (int nt = 0; nt < 4; nt++)
                    mma8(acc[mt][nt], a[mt], bb[nt]);
        }
        __syncthreads();
    }

    // epilogue: C frag layout c0=C[g][2tg], c1=C[g][2tg+1], c2=C[g+8][2tg], c3=C[g+8][2tg+1]
#pragma unroll
    for (int mt = 0; mt < 4; mt++) {
        int m0 = bm + wm + mt * 16 + g;
        int m1 = m0 + 8;
#pragma unroll
        for (int nt = 0; nt < 4; nt++) {
            int n0 = bn + wn + nt * 8 + 2 * tg;
            float b0 = bias[n0], b1 = bias[n0 + 1];
            float v00 = acc[mt][nt][0] + b0;
            float v01 = acc[mt][nt][1] + b1;
            float v10 = acc[mt][nt][2] + b0;
            float v11 = acc[mt][nt][3] + b1;
            if (mode == 0) {
                obase[(size_t)m0 * DMODEL + n0]     = v00;
                obase[(size_t)m0 * DMODEL + n0 + 1] = v01;
                obase[(size_t)m1 * DMODEL + n0]     = v10;
                obase[(size_t)m1 * DMODEL + n0 + 1] = v11;
            } else {
                int h = n0 >> 6, d = n0 & 63;
                {
                    int b_ = m0 >> 11, s = m0 & (SEQ - 1);
                    size_t base = (((size_t)(b_ * NHEADS + h) * SEQ + s) << 6) + d;
                    obase[base] = v00; obase[base + 1] = v01;
                }
                {
                    int b_ = m1 >> 11, s = m1 & (SEQ - 1);
                    size_t base = (((size_t)(b_ * NHEADS + h) * SEQ + s) << 6) + d;
                    obase[base] = v10; obase[base + 1] = v11;
                }
            }
        }
    }
}

// ==================== Flash attention (tf32 mma, fp32 online softmax) ====================
// grid = (B*H, SEQ/64); block = 128 threads (4 warps, each owns 16 query rows)
#define KT    32   // keys per tile
#define PADK  68   // frag-load bank = (4g+tg): conflict-free; rows 16B-aligned
#define PADV  65   // V B-frag bank = (8tg+g) mod 32: conflict-free
#define PADP  36   // P A-frag bank = (4g+tg): conflict-free

__global__ __launch_bounds__(128, 1)
void attn_tf32()
{
    __shared__ uint32_t Ks[KT * PADK];
    __shared__ uint32_t Vs[KT * PADV];
    __shared__ uint32_t Ps[64 * PADP];

    const int bh = blockIdx.x;           // 0..63
    const int qt = blockIdx.y;           // 0..31
    const int b  = bh >> 4;
    const int h  = bh & (NHEADS - 1);
    const float* Qg = g_q + (size_t)bh * SEQ * HDIM;
    const float* Kg = g_k + (size_t)bh * SEQ * HDIM;
    const float* Vg = g_v + (size_t)bh * SEQ * HDIM;

    const int tid  = threadIdx.x;
    const int wid  = tid >> 5;
    const int lane = tid & 31;
    const int g    = lane >> 2;
    const int tg   = lane & 3;
    const int q0   = qt * 64 + wid * 16;

    // Q fragments for the whole kernel (scale 1/sqrt(64) folded in before tf32 cvt)
    uint32_t qa[8][4];
#pragma unroll
    for (int kc = 0; kc < 8; kc++) {
        int col = kc * 8 + tg;
        qa[kc][0] = f2tf(0.125f * Qg[(size_t)(q0 + g)     * HDIM + col]);
        qa[kc][1] = f2tf(0.125f * Qg[(size_t)(q0 + g + 8) * HDIM + col]);
        qa[kc][2] = f2tf(0.125f * Qg[(size_t)(q0 + g)     * HDIM + col + 4]);
        qa[kc][3] = f2tf(0.125f * Qg[(size_t)(q0 + g + 8) * HDIM + col + 4]);
    }

    float o[8][4];
#pragma unroll
    for (int i = 0; i < 8; i++)
#pragma unroll
        for (int j = 0; j < 4; j++) o[i][j] = 0.f;
    float mrow0 = -1e30f, mrow1 = -1e30f, l0 = 0.f, l1 = 0.f;

    for (int t0 = 0; t0 < SEQ; t0 += KT) {
        // load K/V tiles (32 x 64 each), converting to tf32
#pragma unroll
        for (int i = 0; i < 4; i++) {
            int e  = tid + i * 128;        // 0..511
            int r  = e >> 4;               // 0..31
            int c4 = (e & 15) << 2;        // 0..60
            float4 kv = *(const float4*)(Kg + (size_t)(t0 + r) * HDIM + c4);
            uint4  uk = make_uint4(f2tf(kv.x), f2tf(kv.y), f2tf(kv.z), f2tf(kv.w));
            *(uint4*)(&Ks[r * PADK + c4]) = uk;
            float4 vv = *(const float4*)(Vg + (size_t)(t0 + r) * HDIM + c4);
            uint32_t* dv = &Vs[r * PADV + c4];      // PADV=65: unaligned, scalar stores
            dv[0] = f2tf(vv.x); dv[1] = f2tf(vv.y);
            dv[2] = f2tf(vv.z); dv[3] = f2tf(vv.w);
        }
        __syncthreads();

        // S = (Q*0.125) @ K^T : warp computes 16 rows x 32 keys (4 n-tiles)
        float s[4][4];
#pragma unroll
        for (int nt = 0; nt < 4; nt++)
#pragma unroll
            for (int j = 0; j < 4; j++) s[nt][j] = 0.f;
#pragma unroll
        for (int kc = 0; kc < 8; kc++) {
#pragma unroll
            for (int nt = 0; nt < 4; nt++) {
                uint32_t bf[2];
                int kr = nt * 8 + g;
                bf[0] = Ks[kr * PADK + kc * 8 + tg];
                bf[1] = Ks[kr * PADK + kc * 8 + tg + 4];
                mma8(s[nt], qa[kc], bf);
            }
        }

        // online softmax (row g -> c0,c1 ; row g+8 -> c2,c3)
        float rm0 = -1e30f, rm1 = -1e30f;
#pragma unroll
        for (int nt = 0; nt < 4; nt++) {
            rm0 = fmaxf(rm0, fmaxf(s[nt][0], s[nt][1]));
            rm1 = fmaxf(rm1, fmaxf(s[nt][2], s[nt][3]));
        }
        rm0 = fmaxf(rm0, __shfl_xor_sync(0xffffffffu, rm0, 1));
        rm0 = fmaxf(rm0, __shfl_xor_sync(0xffffffffu, rm0, 2));
        rm1 = fmaxf(rm1, __shfl_xor_sync(0xffffffffu, rm1, 1));
        rm1 = fmaxf(rm1, __shfl_xor_sync(0xffffffffu, rm1, 2));
        float mn0 = fmaxf(mrow0, rm0), mn1 = fmaxf(mrow1, rm1);
        float al0 = __expf(mrow0 - mn0), al1 = __expf(mrow1 - mn1);
        mrow0 = mn0; mrow1 = mn1;

        float rs0 = 0.f, rs1 = 0.f;
#pragma unroll
        for (int nt = 0; nt < 4; nt++) {
            s[nt][0] = __expf(s[nt][0] - mn0); rs0 += s[nt][0];
            s[nt][1] = __expf(s[nt][1] - mn0); rs0 += s[nt][1];
            s[nt][2] = __expf(s[nt][2] - mn1); rs1 += s[nt][2];
            s[nt][3] = __expf(s[nt][3] - mn1); rs1 += s[nt][3];
        }
        rs0 += __shfl_xor_sync(0xffffffffu, rs0, 1);
        rs0 += __shfl_xor_sync(0xffffffffu, rs0, 2);
        rs1 += __shfl_xor_sync(0xffffffffu, rs1, 1);
        rs1 += __shfl_xor_sync(0xffffffffu, rs1, 2);
        l0 = l0 * al0 + rs0;
        l1 = l1 * al1 + rs1;

#pragma unroll
        for (int nt2 = 0; nt2 < 8; nt2++) {
            o[nt2][0] *= al0; o[nt2][1] *= al0;
            o[nt2][2] *= al1; o[nt2][3] *= al1;
        }

        // P (C-frag layout) -> smem, then reload as A fragments (warp-private rows)
        const int pr0 = wid * 16 + g, pr1 = pr0 + 8;
#pragma unroll
        for (int nt = 0; nt < 4; nt++) {
            int col = nt * 8 + 2 * tg;
            Ps[pr0 * PADP + col]     = f2tf(s[nt][0]);
            Ps[pr0 * PADP + col + 1] = f2tf(s[nt][1]);
            Ps[pr1 * PADP + col]     = f2tf(s[nt][2]);
            Ps[pr1 * PADP + col + 1] = f2tf(s[nt][3]);
        }
        __syncwarp();

        // O += P @ V  (k = 32 keys in 4 chunks; n = 64 dims in 8 tiles)
#pragma unroll
        for (int kc2 = 0; kc2 < 4; kc2++) {
            uint32_t pa[4];
            pa[0] = Ps[pr0 * PADP + kc2 * 8 + tg];
            pa[1] = Ps[pr1 * PADP + kc2 * 8 + tg];
            pa[2] = Ps[pr0 * PADP + kc2 * 8 + tg + 4];
            pa[3] = Ps[pr1 * PADP + kc2 * 8 + tg + 4];
#pragma unroll
            for (int nt2 = 0; nt2 < 8; nt2++) {
                uint32_t bf[2];
                bf[0] = Vs[(kc2 * 8 + tg)     * PADV + nt2 * 8 + g];
                bf[1] = Vs[(kc2 * 8 + tg + 4) * PADV + nt2 * 8 + g];
                mma8(o[nt2], pa, bf);
            }
        }
        __syncthreads();
    }

    // finalize and write to [B, S, D] layout
    const float inv0 = 1.f / l0, inv1 = 1.f / l1;
    const int s0 = q0 + g, s1 = s0 + 8;
#pragma unroll
    for (int nt2 = 0; nt2 < 8; nt2++) {
        int d = nt2 * 8 + 2 * tg;
        size_t base0 = ((size_t)(b * SEQ + s0) * DMODEL) + h * HDIM + d;
        size_t base1 = ((size_t)(b * SEQ + s1) * DMODEL) + h * HDIM + d;
        g_ao[base0]     = o[nt2][0] * inv0;
        g_ao[base0 + 1] = o[nt2][1] * inv0;
        g_ao[base1]     = o[nt2][2] * inv1;
        g_ao[base1 + 1] = o[nt2][3] * inv1;
    }
}

// ==================== launch ====================
extern "C" void kernel_launch(void* const* d_in, const int* in_sizes, int n_in,
                              void* d_out, int out_size)
{
    const float* query = (const float*)d_in[0];
    const float* key_  = (const float*)d_in[1];
    const float* value = (const float*)d_in[2];
    const float* Wq = (const float*)d_in[3];
    const float* bq = (const float*)d_in[4];
    const float* Wk = (const float*)d_in[5];
    const float* bk = (const float*)d_in[6];
    const float* Wv = (const float*)d_in[7];
    const float* bv = (const float*)d_in[8];
    const float* Wo = (const float*)d_in[9];
    const float* bo = (const float*)d_in[10];
    float* out = (float*)d_out;

    dim3 gg(MTOT / GBM, DMODEL / GBN);   // (64, 8)
    gemm_tf32<<<gg, 256>>>(query, Wq, bq, nullptr, 1);
    gemm_tf32<<<gg, 256>>>(key_,  Wk, bk, nullptr, 2);
    gemm_tf32<<<gg, 256>>>(value, Wv, bv, nullptr, 3);
    attn_tf32<<<dim3(BATCH * NHEADS, SEQ / 64), 128>>>();
    gemm_tf32<<<gg, 256>>>(nullptr, Wo, bo, out, 0);
}

// round 12
// speedup vs baseline: 1.0029x; 1.0029x over previous
#include <cuda_runtime.h>
#include <cstdint>

// Problem constants
#define BATCH   4
#define SEQ     2048
#define DMODEL  1024
#define NHEADS  16
#define HDIM    64
#define MTOT    (BATCH * SEQ)   // 8192

// -------------------- scratch (device globals; no allocation) --------------------
__device__ __align__(16) float g_q[BATCH * NHEADS * SEQ * HDIM];   // [B*H, S, 64]
__device__ __align__(16) float g_k[BATCH * NHEADS * SEQ * HDIM];
__device__ __align__(16) float g_v[BATCH * NHEADS * SEQ * HDIM];
__device__ __align__(16) float g_ao[MTOT * DMODEL];                // [B, S, D]

// -------------------- helpers --------------------
__device__ __forceinline__ uint32_t f2tf(float x) {
    uint32_t r;
    asm("cvt.rna.tf32.f32 %0, %1;" : "=r"(r) : "f"(x));
    return r;
}

// D += A(16x8) * B(8x8), tf32 inputs, f32 accumulate
__device__ __forceinline__ void mma8(float* c, const uint32_t* a, const uint32_t* b) {
    asm volatile(
        "mma.sync.aligned.m16n8k8.row.col.f32.tf32.tf32.f32 "
        "{%0,%1,%2,%3}, {%4,%5,%6,%7}, {%8,%9}, {%0,%1,%2,%3};\n"
        : "+f"(c[0]), "+f"(c[1]), "+f"(c[2]), "+f"(c[3])
        : "r"(a[0]), "r"(a[1]), "r"(a[2]), "r"(a[3]),
          "r"(b[0]), "r"(b[1]));
}

// ==================== TF32 GEMM: C[M,N] = X[M,K] @ W[N,K]^T + bias ====================
// mode: 0 = plain [M,N] row-major into `out` (X==nullptr means read g_ao)
//       1/2/3 = scatter into g_q/g_k/g_v with [B*H, S, 64] layout
#define GBM  128
#define GBN  128
#define GBK  32
#define GPAD 36   // 36*4B rows: frag load bank = (4g+tg) -> conflict-free; rows 16B-aligned

__global__ __launch_bounds__(256, 1)
void gemm_tf32(const float* __restrict__ X, const float* __restrict__ W,
               const float* __restrict__ bias, float* __restrict__ out, int mode)
{
    __shared__ uint32_t As[GBM * GPAD];
    __shared__ uint32_t Bs[GBN * GPAD];

    const float* Xp = X ? X : g_ao;
    float* obase;
    if (mode == 1)      obase = g_q;
    else if (mode == 2) obase = g_k;
    else if (mode == 3) obase = g_v;
    else                obase = out;

    const int tid  = threadIdx.x;
    const int lane = tid & 31;
    const int wid  = tid >> 5;
    const int g    = lane >> 2;
    const int tg   = lane & 3;
    const int wm   = (wid >> 2) * 64;   // warp M offset (2 warps in M)
    const int wn   = (wid & 3) * 32;    // warp N offset (4 warps in N)
    const int bm   = blockIdx.x * GBM;
    const int bn   = blockIdx.y * GBN;

    float acc[4][4][4];
#pragma unroll
    for (int i = 0; i < 4; i++)
#pragma unroll
        for (int j = 0; j < 4; j++)
#pragma unroll
            for (int r = 0; r < 4; r++) acc[i][j][r] = 0.f;

    for (int k0 = 0; k0 < DMODEL; k0 += GBK) {
        // global -> smem (convert to tf32 on the way); 1024 float4 per tile, 4/thread
#pragma unroll
        for (int i = 0; i < 4; i++) {
            int e   = tid + i * 256;
            int row = e >> 3;
            int c4  = (e & 7) << 2;
            float4 va = *(const float4*)(Xp + (size_t)(bm + row) * DMODEL + k0 + c4);
            uint4  ua = make_uint4(f2tf(va.x), f2tf(va.y), f2tf(va.z), f2tf(va.w));
            *(uint4*)(&As[row * GPAD + c4]) = ua;
            float4 vb = *(const float4*)(W + (size_t)(bn + row) * DMODEL + k0 + c4);
            uint4  ub = make_uint4(f2tf(vb.x), f2tf(vb.y), f2tf(vb.z), f2tf(vb.w));
            *(uint4*)(&Bs[row * GPAD + c4]) = ub;
        }
        __syncthreads();

#pragma unroll
        for (int ks = 0; ks < 4; ks++) {
            const int kk = ks * 8;
            uint32_t a[4][4], bb[4][2];
#pragma unroll
            for (int mt = 0; mt < 4; mt++) {
                int r0 = wm + mt * 16;
                a[mt][0] = As[(r0 + g)     * GPAD + kk + tg];
                a[mt][1] = As[(r0 + g + 8) * GPAD + kk + tg];
                a[mt][2] = As[(r0 + g)     * GPAD + kk + tg + 4];
                a[mt][3] = As[(r0 + g + 8) * GPAD + kk + tg + 4];
            }
#pragma unroll
            for (int nt = 0; nt < 4; nt++) {
                int rn = wn + nt * 8 + g;
                bb[nt][0] = Bs[rn * GPAD + kk + tg];
                bb[nt][1] = Bs[rn * GPAD + kk + tg + 4];
            }
#pragma unroll
            for (int mt = 0; mt < 4; mt++)
#pragma unroll
                for (int nt = 0; nt < 4; nt++)
                    mma8(acc[mt][nt], a[mt], bb[nt]);
        }
        __syncthreads();
    }

    // epilogue: C frag layout c0=C[g][2tg], c1=C[g][2tg+1], c2=C[g+8][2tg], c3=C[g+8][2tg+1]
#pragma unroll
    for (int mt = 0; mt < 4; mt++) {
        int m0 = bm + wm + mt * 16 + g;
        int m1 = m0 + 8;
#pragma unroll
        for (int nt = 0; nt < 4; nt++) {
            int n0 = bn + wn + nt * 8 + 2 * tg;
            float b0 = bias[n0], b1 = bias[n0 + 1];
            float v00 = acc[mt][nt][0] + b0;
            float v01 = acc[mt][nt][1] + b1;
            float v10 = acc[mt][nt][2] + b0;
            float v11 = acc[mt][nt][3] + b1;
            if (mode == 0) {
                obase[(size_t)m0 * DMODEL + n0]     = v00;
                obase[(size_t)m0 * DMODEL + n0 + 1] = v01;
                obase[(size_t)m1 * DMODEL + n0]     = v10;
                obase[(size_t)m1 * DMODEL + n0 + 1] = v11;
            } else {
                int h = n0 >> 6, d = n0 & 63;
                {
                    int b_ = m0 >> 11, s = m0 & (SEQ - 1);
                    size_t base = (((size_t)(b_ * NHEADS + h) * SEQ + s) << 6) + d;
                    obase[base] = v00; obase[base + 1] = v01;
                }
                {
                    int b_ = m1 >> 11, s = m1 & (SEQ - 1);
                    size_t base = (((size_t)(b_ * NHEADS + h) * SEQ + s) << 6) + d;
                    obase[base] = v10; obase[base + 1] = v11;
                }
            }
        }
    }
}

// ==================== Flash attention (tf32 mma, fp32 online softmax) ====================
// grid = (B*H, SEQ/64); block = 128 threads (4 warps, each owns 16 query rows)
#define KT    32   // keys per tile
#define PADK  68   // frag-load bank = (4g+tg): conflict-free; rows 16B-aligned
#define PADV  65   // V B-frag bank = (8tg+g) mod 32: conflict-free
#define PADP  36   // P A-frag bank = (4g+tg): conflict-free

__global__ __launch_bounds__(128, 1)
void attn_tf32()
{
    __shared__ uint32_t Ks[KT * PADK];
    __shared__ uint32_t Vs[KT * PADV];
    __shared__ uint32_t Ps[64 * PADP];

    const int bh = blockIdx.x;           // 0..63
    const int qt = blockIdx.y;           // 0..31
    const int b  = bh >> 4;
    const int h  = bh & (NHEADS - 1);
    const float* Qg = g_q + (size_t)bh * SEQ * HDIM;
    const float* Kg = g_k + (size_t)bh * SEQ * HDIM;
    const float* Vg = g_v + (size_t)bh * SEQ * HDIM;

    const int tid  = threadIdx.x;
    const int wid  = tid >> 5;
    const int lane = tid & 31;
    const int g    = lane >> 2;
    const int tg   = lane & 3;
    const int q0   = qt * 64 + wid * 16;

    // Q fragments for the whole kernel (scale 1/sqrt(64) folded in before tf32 cvt)
    uint32_t qa[8][4];
#pragma unroll
    for (int kc = 0; kc < 8; kc++) {
        int col = kc * 8 + tg;
        qa[kc][0] = f2tf(0.125f * Qg[(size_t)(q0 + g)     * HDIM + col]);
        qa[kc][1] = f2tf(0.125f * Qg[(size_t)(q0 + g + 8) * HDIM + col]);
        qa[kc][2] = f2tf(0.125f * Qg[(size_t)(q0 + g)     * HDIM + col + 4]);
        qa[kc][3] = f2tf(0.125f * Qg[(size_t)(q0 + g + 8) * HDIM + col + 4]);
    }

    float o[8][4];
#pragma unroll
    for (int i = 0; i < 8; i++)
#pragma unroll
        for (int j = 0; j < 4; j++) o[i][j] = 0.f;
    float mrow0 = -1e30f, mrow1 = -1e30f, l0 = 0.f, l1 = 0.f;

    for (int t0 = 0; t0 < SEQ; t0 += KT) {
        // load K/V tiles (32 x 64 each), converting to tf32
#pragma unroll
        for (int i = 0; i < 4; i++) {
            int e  = tid + i * 128;        // 0..511
            int r  = e >> 4;               // 0..31
            int c4 = (e & 15) << 2;        // 0..60
            float4 kv = *(const float4*)(Kg + (size_t)(t0 + r) * HDIM + c4);
            uint4  uk = make_uint4(f2tf(kv.x), f2tf(kv.y), f2tf(kv.z), f2tf(kv.w));
            *(uint4*)(&Ks[r * PADK + c4]) = uk;
            float4 vv = *(const float4*)(Vg + (size_t)(t0 + r) * HDIM + c4);
            uint32_t* dv = &Vs[r * PADV + c4];      // PADV=65: unaligned, scalar stores
            dv[0] = f2tf(vv.x); dv[1] = f2tf(vv.y);
            dv[2] = f2tf(vv.z); dv[3] = f2tf(vv.w);
        }
        __syncthreads();

        // S = (Q*0.125) @ K^T : warp computes 16 rows x 32 keys (4 n-tiles)
        float s[4][4];
#pragma unroll
        for (int nt = 0; nt < 4; nt++)
#pragma unroll
            for (int j = 0; j < 4; j++) s[nt][j] = 0.f;
#pragma unroll
        for (int kc = 0; kc < 8; kc++) {
#pragma unroll
            for (int nt = 0; nt < 4; nt++) {
                uint32_t bf[2];
                int kr = nt * 8 + g;
                bf[0] = Ks[kr * PADK + kc * 8 + tg];
                bf[1] = Ks[kr * PADK + kc * 8 + tg + 4];
                mma8(s[nt], qa[kc], bf);
            }
        }

        // online softmax (row g -> c0,c1 ; row g+8 -> c2,c3)
        float rm0 = -1e30f, rm1 = -1e30f;
#pragma unroll
        for (int nt = 0; nt < 4; nt++) {
            rm0 = fmaxf(rm0, fmaxf(s[nt][0], s[nt][1]));
            rm1 = fmaxf(rm1, fmaxf(s[nt][2], s[nt][3]));
        }
        rm0 = fmaxf(rm0, __shfl_xor_sync(0xffffffffu, rm0, 1));
        rm0 = fmaxf(rm0, __shfl_xor_sync(0xffffffffu, rm0, 2));
        rm1 = fmaxf(rm1, __shfl_xor_sync(0xffffffffu, rm1, 1));
        rm1 = fmaxf(rm1, __shfl_xor_sync(0xffffffffu, rm1, 2));
        float mn0 = fmaxf(mrow0, rm0), mn1 = fmaxf(mrow1, rm1);
        float al0 = __expf(mrow0 - mn0), al1 = __expf(mrow1 - mn1);
        mrow0 = mn0; mrow1 = mn1;

        float rs0 = 0.f, rs1 = 0.f;
#pragma unroll
        for (int nt = 0; nt < 4; nt++) {
            s[nt][0] = __expf(s[nt][0] - mn0); rs0 += s[nt][0];
            s[nt][1] = __expf(s[nt][1] - mn0); rs0 += s[nt][1];
            s[nt][2] = __expf(s[nt][2] - mn1); rs1 += s[nt][2];
            s[nt][3] = __expf(s[nt][3] - mn1); rs1 += s[nt][3];
        }
        rs0 += __shfl_xor_sync(0xffffffffu, rs0, 1);
        rs0 += __shfl_xor_sync(0xffffffffu, rs0, 2);
        rs1 += __shfl_xor_sync(0xffffffffu, rs1, 1);
        rs1 += __shfl_xor_sync(0xffffffffu, rs1, 2);
        l0 = l0 * al0 + rs0;
        l1 = l1 * al1 + rs1;

#pragma unroll
        for (int nt2 = 0; nt2 < 8; nt2++) {
            o[nt2][0] *= al0; o[nt2][1] *= al0;
            o[nt2][2] *= al1; o[nt2][3] *= al1;
        }

        // P (C-frag layout) -> smem, then reload as A fragments (warp-private rows)
        const int pr0 = wid * 16 + g, pr1 = pr0 + 8;
#pragma unroll
        for (int nt = 0; nt < 4; nt++) {
            int col = nt * 8 + 2 * tg;
            Ps[pr0 * PADP + col]     = f2tf(s[nt][0]);
            Ps[pr0 * PADP + col + 1] = f2tf(s[nt][1]);
            Ps[pr1 * PADP + col]     = f2tf(s[nt][2]);
            Ps[pr1 * PADP + col + 1] = f2tf(s[nt][3]);
        }
        __syncwarp();

        // O += P @ V  (k = 32 keys in 4 chunks; n = 64 dims in 8 tiles)
#pragma unroll
        for (int kc2 = 0; kc2 < 4; kc2++) {
            uint32_t pa[4];
            pa[0] = Ps[pr0 * PADP + kc2 * 8 + tg];
            pa[1] = Ps[pr1 * PADP + kc2 * 8 + tg];
            pa[2] = Ps[pr0 * PADP + kc2 * 8 + tg + 4];
            pa[3] = Ps[pr1 * PADP + kc2 * 8 + tg + 4];
#pragma unroll
            for (int nt2 = 0; nt2 < 8; nt2++) {
                uint32_t bf[2];
                bf[0] = Vs[(kc2 * 8 + tg)     * PADV + nt2 * 8 + g];
                bf[1] = Vs[(kc2 * 8 + tg + 4) * PADV + nt2 * 8 + g];
                mma8(o[nt2], pa, bf);
            }
        }
        __syncthreads();
    }

    // finalize and write to [B, S, D] layout
    const float inv0 = 1.f / l0, inv1 = 1.f / l1;
    const int s0 = q0 + g, s1 = s0 + 8;
#pragma unroll
    for (int nt2 = 0; nt2 < 8; nt2++) {
        int d = nt2 * 8 + 2 * tg;
        size_t base0 = ((size_t)(b * SEQ + s0) * DMODEL) + h * HDIM + d;
        size_t base1 = ((size_t)(b * SEQ + s1) * DMODEL) + h * HDIM + d;
        g_ao[base0]     = o[nt2][0] * inv0;
        g_ao[base0 + 1] = o[nt2][1] * inv0;
        g_ao[base1]     = o[nt2][2] * inv1;
        g_ao[base1 + 1] = o[nt2][3] * inv1;
    }
}

// ==================== launch ====================
extern "C" void kernel_launch(void* const* d_in, const int* in_sizes, int n_in,
                              void* d_out, int out_size)
{
    const float* query = (const float*)d_in[0];
    const float* key_  = (const float*)d_in[1];
    const float* value = (const float*)d_in[2];
    const float* Wq = (const float*)d_in[3];
    const float* bq = (const float*)d_in[4];
    const float* Wk = (const float*)d_in[5];
    const float* bk = (const float*)d_in[6];
    const float* Wv = (const float*)d_in[7];
    const float* bv = (const float*)d_in[8];
    const float* Wo = (const float*)d_in[9];
    const float* bo = (const float*)d_in[10];
    float* out = (float*)d_out;

    dim3 gg(MTOT / GBM, DMODEL / GBN);   // (64, 8)
    gemm_tf32<<<gg, 256>>>(query, Wq, bq, nullptr, 1);
    gemm_tf32<<<gg, 256>>>(key_,  Wk, bk, nullptr, 2);
    gemm_tf32<<<gg, 256>>>(value, Wv, bv, nullptr, 3);
    attn_tf32<<<dim3(BATCH * NHEADS, SEQ / 64), 128>>>();
    gemm_tf32<<<gg, 256>>>(nullptr, Wo, bo, out, 0);
}